// round 1
// baseline (speedup 1.0000x reference)
#include <cuda_runtime.h>
#include <cuda_bf16.h>
#include <cstdint>

// Problem constants
#define BB 2
#define SS 2048
#define DD 1024
#define HH 16
#define HD 64
#define NEG (-1.0e9f)

// Scratch (device globals; allocation inside kernel_launch is forbidden)
__device__ float g_q[BB * HH * SS * HD];     // [B,H,S,HD]
__device__ float g_k[BB * HH * SS * HD];
__device__ float g_v[BB * HH * SS * HD];
__device__ float g_att[BB * SS * DD];        // [B,S,D] attention output

// ---------------------------------------------------------------------------
// GEMM 1: fused QKV projection.  C = x @ W + b, remapped to [B,H,S,HD].
// Tile 64x64, BK=16, 256 threads, 4x4 per thread.
// gridDim = (N/64=16, M/64=64, 3)  z picks q/k/v.
// ---------------------------------------------------------------------------
__global__ __launch_bounds__(256) void qkv_gemm(
    const float* __restrict__ x,
    const float* __restrict__ Wq, const float* __restrict__ bq,
    const float* __restrict__ Wk, const float* __restrict__ bk,
    const float* __restrict__ Wv, const float* __restrict__ bv)
{
    const int z = blockIdx.z;
    const float* __restrict__ W = (z == 0) ? Wq : (z == 1) ? Wk : Wv;
    const float* __restrict__ bias = (z == 0) ? bq : (z == 1) ? bk : bv;
    float* __restrict__ out = (z == 0) ? g_q : (z == 1) ? g_k : g_v;

    __shared__ float As[16][68];   // [k][m] transposed
    __shared__ float Bs[16][68];   // [k][n]

    const int tid = threadIdx.x;
    const int tx = tid % 16, ty = tid / 16;
    const int m0 = blockIdx.y * 64;
    const int n0 = blockIdx.x * 64;

    const int la_r = tid / 4;            // 0..63 (m within tile)
    const int la_c = (tid % 4) * 4;      // 0..12 (k within tile)
    const int lb_r = tid / 16;           // 0..15 (k within tile)
    const int lb_c = (tid % 16) * 4;     // 0..60 (n within tile)

    float acc[4][4];
#pragma unroll
    for (int i = 0; i < 4; i++)
#pragma unroll
        for (int j = 0; j < 4; j++) acc[i][j] = 0.f;

    for (int k0 = 0; k0 < DD; k0 += 16) {
        float4 av = *(const float4*)&x[(size_t)(m0 + la_r) * DD + k0 + la_c];
        As[la_c + 0][la_r] = av.x;
        As[la_c + 1][la_r] = av.y;
        As[la_c + 2][la_r] = av.z;
        As[la_c + 3][la_r] = av.w;
        *(float4*)&Bs[lb_r][lb_c] =
            *(const float4*)&W[(size_t)(k0 + lb_r) * DD + n0 + lb_c];
        __syncthreads();
#pragma unroll
        for (int kk = 0; kk < 16; kk++) {
            float4 a = *(const float4*)&As[kk][ty * 4];
            float4 b = *(const float4*)&Bs[kk][tx * 4];
            float ar[4] = {a.x, a.y, a.z, a.w};
            float br[4] = {b.x, b.y, b.z, b.w};
#pragma unroll
            for (int i = 0; i < 4; i++)
#pragma unroll
                for (int j = 0; j < 4; j++) acc[i][j] += ar[i] * br[j];
        }
        __syncthreads();
    }

    // Epilogue: add bias, remap to [B,H,S,HD]. n-tile == one head (64==HD).
    const int h = blockIdx.x;            // n0/64
    float bb[4];
#pragma unroll
    for (int j = 0; j < 4; j++) bb[j] = bias[n0 + tx * 4 + j];
#pragma unroll
    for (int i = 0; i < 4; i++) {
        int m = m0 + ty * 4 + i;
        int b = m / SS, s = m % SS;
        float4 o;
        o.x = acc[i][0] + bb[0];
        o.y = acc[i][1] + bb[1];
        o.z = acc[i][2] + bb[2];
        o.w = acc[i][3] + bb[3];
        *(float4*)&out[(size_t)((b * HH + h) * SS + s) * HD + tx * 4] = o;
    }
}

// ---------------------------------------------------------------------------
// Flash-attention style kernel. One block = one 64-row Q tile of one (b,h).
// grid = (S/64=32, H, B), 256 threads (16x16), 4x4 register micro-tiles.
// Online softmax; causal tile skipping (only jt <= qt).
// ---------------------------------------------------------------------------
#define SQ 68   // stride for Qs/Ks/Vs (float4-aligned, conflict-free vec loads)
#define SP 65   // stride for Ps (odd -> conflict-free row scans)

__global__ __launch_bounds__(256) void attn_kernel(const float* __restrict__ mask)
{
    extern __shared__ float sm[];
    float* Qs = sm;                 // transposed: Qs[d*SQ + q]
    float* Ks = Qs + 64 * SQ;       // transposed: Ks[d*SQ + k]
    float* Vs = Ks + 64 * SQ;       // Vs[k*SQ + d]
    float* Ps = Vs + 64 * SQ;       // Ps[q*SP + k]
    float* marr = Ps + 64 * SP;
    float* larr = marr + 64;
    float* osc  = larr + 64;
    float* madd = osc + 64;

    const int qt = blockIdx.x, h = blockIdx.y, b = blockIdx.z;
    const int tid = threadIdx.x, tx = tid % 16, ty = tid / 16;

    const float* qbase = g_q + (size_t)((b * HH + h) * SS + qt * 64) * HD;

    // Load Q tile (transposed into Qs)
#pragma unroll
    for (int p = 0; p < 4; p++) {
        int lin = p * 1024 + tid * 4;
        int r = lin / 64, d = lin % 64;
        float4 v = *(const float4*)&qbase[r * 64 + d];
        Qs[(d + 0) * SQ + r] = v.x;
        Qs[(d + 1) * SQ + r] = v.y;
        Qs[(d + 2) * SQ + r] = v.z;
        Qs[(d + 3) * SQ + r] = v.w;
    }
    if (tid < 64) { marr[tid] = -1e30f; larr[tid] = 0.f; }

    float O[4][4];
#pragma unroll
    for (int i = 0; i < 4; i++)
#pragma unroll
        for (int j = 0; j < 4; j++) O[i][j] = 0.f;

    __syncthreads();

    for (int jt = 0; jt <= qt; jt++) {
        const float* kbase = g_k + (size_t)((b * HH + h) * SS + jt * 64) * HD;
        const float* vbase = g_v + (size_t)((b * HH + h) * SS + jt * 64) * HD;
#pragma unroll
        for (int p = 0; p < 4; p++) {
            int lin = p * 1024 + tid * 4;
            int r = lin / 64, d = lin % 64;
            float4 v = *(const float4*)&kbase[r * 64 + d];
            Ks[(d + 0) * SQ + r] = v.x;
            Ks[(d + 1) * SQ + r] = v.y;
            Ks[(d + 2) * SQ + r] = v.z;
            Ks[(d + 3) * SQ + r] = v.w;
            *(float4*)&Vs[r * SQ + d] = *(const float4*)&vbase[r * 64 + d];
        }
        if (tid < 64)
            madd[tid] = (1.f - mask[b * SS + jt * 64 + tid]) * NEG;
        __syncthreads();

        // S = Q K^T
        float s[4][4];
#pragma unroll
        for (int i = 0; i < 4; i++)
#pragma unroll
            for (int j = 0; j < 4; j++) s[i][j] = 0.f;
#pragma unroll 8
        for (int d = 0; d < 64; d++) {
            float4 a = *(const float4*)&Qs[d * SQ + ty * 4];
            float4 bvec = *(const float4*)&Ks[d * SQ + tx * 4];
            float ar[4] = {a.x, a.y, a.z, a.w};
            float br[4] = {bvec.x, bvec.y, bvec.z, bvec.w};
#pragma unroll
            for (int i = 0; i < 4; i++)
#pragma unroll
                for (int j = 0; j < 4; j++) s[i][j] += ar[i] * br[j];
        }

        // scale + causal + padding mask, store raw scores to Ps
        const bool diag = (jt == qt);
#pragma unroll
        for (int i = 0; i < 4; i++) {
            int qg = ty * 4 + i;              // local q (same tile base)
#pragma unroll
            for (int j = 0; j < 4; j++) {
                int kl = tx * 4 + j;
                float v;
                if (diag && (kl > qg)) v = NEG;       // score*0 + NEG
                else                   v = s[i][j] * 0.125f;
                v += madd[kl];
                Ps[qg * SP + kl] = v;
            }
        }
        __syncthreads();

        // Row-wise online softmax update (64 threads, one per row)
        if (tid < 64) {
            float mx = -1e30f;
#pragma unroll 8
            for (int k = 0; k < 64; k++) mx = fmaxf(mx, Ps[tid * SP + k]);
            float m_old = marr[tid];
            float m_new = fmaxf(m_old, mx);
            float sum = 0.f;
#pragma unroll 8
            for (int k = 0; k < 64; k++) {
                float p = __expf(Ps[tid * SP + k] - m_new);
                Ps[tid * SP + k] = p;
                sum += p;
            }
            float sc = __expf(m_old - m_new);
            osc[tid] = sc;
            larr[tid] = larr[tid] * sc + sum;
            marr[tid] = m_new;
        }
        __syncthreads();

        // Rescale O, then O += P @ V
        float scl[4];
#pragma unroll
        for (int i = 0; i < 4; i++) scl[i] = osc[ty * 4 + i];
#pragma unroll
        for (int i = 0; i < 4; i++)
#pragma unroll
            for (int j = 0; j < 4; j++) O[i][j] *= scl[i];

#pragma unroll 8
        for (int k = 0; k < 64; k++) {
            float4 bvec = *(const float4*)&Vs[k * SQ + tx * 4];
            float br[4] = {bvec.x, bvec.y, bvec.z, bvec.w};
#pragma unroll
            for (int i = 0; i < 4; i++) {
                float a = Ps[(ty * 4 + i) * SP + k];
#pragma unroll
                for (int j = 0; j < 4; j++) O[i][j] += a * br[j];
            }
        }
        __syncthreads();   // protect Ks/Vs/Ps before next tile's loads
    }

    // Normalize and write to g_att [B,S,D]
#pragma unroll
    for (int i = 0; i < 4; i++) {
        int ql = ty * 4 + i;
        int sg = qt * 64 + ql;
        float il = 1.f / larr[ql];
        float4 o;
        o.x = O[i][0] * il;
        o.y = O[i][1] * il;
        o.z = O[i][2] * il;
        o.w = O[i][3] * il;
        *(float4*)&g_att[(size_t)(b * SS + sg) * DD + h * HD + tx * 4] = o;
    }
}

// ---------------------------------------------------------------------------
// GEMM 2: output projection.  out = g_att @ Wo + bo, [B*S, D].
// ---------------------------------------------------------------------------
__global__ __launch_bounds__(256) void oproj_gemm(
    const float* __restrict__ Wo, const float* __restrict__ bo,
    float* __restrict__ out)
{
    __shared__ float As[16][68];
    __shared__ float Bs[16][68];

    const int tid = threadIdx.x;
    const int tx = tid % 16, ty = tid / 16;
    const int m0 = blockIdx.y * 64;
    const int n0 = blockIdx.x * 64;

    const int la_r = tid / 4;
    const int la_c = (tid % 4) * 4;
    const int lb_r = tid / 16;
    const int lb_c = (tid % 16) * 4;

    float acc[4][4];
#pragma unroll
    for (int i = 0; i < 4; i++)
#pragma unroll
        for (int j = 0; j < 4; j++) acc[i][j] = 0.f;

    for (int k0 = 0; k0 < DD; k0 += 16) {
        float4 av = *(const float4*)&g_att[(size_t)(m0 + la_r) * DD + k0 + la_c];
        As[la_c + 0][la_r] = av.x;
        As[la_c + 1][la_r] = av.y;
        As[la_c + 2][la_r] = av.z;
        As[la_c + 3][la_r] = av.w;
        *(float4*)&Bs[lb_r][lb_c] =
            *(const float4*)&Wo[(size_t)(k0 + lb_r) * DD + n0 + lb_c];
        __syncthreads();
#pragma unroll
        for (int kk = 0; kk < 16; kk++) {
            float4 a = *(const float4*)&As[kk][ty * 4];
            float4 b = *(const float4*)&Bs[kk][tx * 4];
            float ar[4] = {a.x, a.y, a.z, a.w};
            float br[4] = {b.x, b.y, b.z, b.w};
#pragma unroll
            for (int i = 0; i < 4; i++)
#pragma unroll
                for (int j = 0; j < 4; j++) acc[i][j] += ar[i] * br[j];
        }
        __syncthreads();
    }

    float bb[4];
#pragma unroll
    for (int j = 0; j < 4; j++) bb[j] = bo[n0 + tx * 4 + j];
#pragma unroll
    for (int i = 0; i < 4; i++) {
        int m = m0 + ty * 4 + i;
        float4 o;
        o.x = acc[i][0] + bb[0];
        o.y = acc[i][1] + bb[1];
        o.z = acc[i][2] + bb[2];
        o.w = acc[i][3] + bb[3];
        *(float4*)&out[(size_t)m * DD + n0 + tx * 4] = o;
    }
}

// ---------------------------------------------------------------------------
extern "C" void kernel_launch(void* const* d_in, const int* in_sizes, int n_in,
                              void* d_out, int out_size)
{
    const float* x    = (const float*)d_in[0];
    const float* mask = (const float*)d_in[1];
    const float* Wq   = (const float*)d_in[2];
    const float* bq   = (const float*)d_in[3];
    const float* Wk   = (const float*)d_in[4];
    const float* bk   = (const float*)d_in[5];
    const float* Wv   = (const float*)d_in[6];
    const float* bv   = (const float*)d_in[7];
    const float* Wo   = (const float*)d_in[8];
    const float* bo   = (const float*)d_in[9];
    float* out = (float*)d_out;

    // Attention kernel needs > 48KB dynamic smem
    const int smem_bytes = (3 * 64 * SQ + 64 * SP + 4 * 64) * sizeof(float);
    cudaFuncSetAttribute(attn_kernel,
                         cudaFuncAttributeMaxDynamicSharedMemorySize,
                         smem_bytes);

    dim3 gq(DD / 64, (BB * SS) / 64, 3);
    qkv_gemm<<<gq, 256>>>(x, Wq, bq, Wk, bk, Wv, bv);

    dim3 ga(SS / 64, HH, BB);
    attn_kernel<<<ga, 256, smem_bytes>>>(mask);

    dim3 go(DD / 64, (BB * SS) / 64);
    oproj_gemm<<<go, 256>>>(Wo, bo, out);
}

// round 3
// speedup vs baseline: 1.7021x; 1.7021x over previous
#include <cuda_runtime.h>
#include <cuda_bf16.h>
#include <cstdint>

// Problem constants
#define BB 2
#define SS 2048
#define DD 1024
#define HH 16
#define HD 64
#define NEG (-1.0e9f)

// Scratch (device globals)
__device__ float g_q[BB * HH * SS * HD];     // [B,H,S,HD]
__device__ float g_k[BB * HH * SS * HD];
__device__ float g_v[BB * HH * SS * HD];
__device__ float g_att[BB * SS * DD];        // [B,S,D]

// ===========================================================================
// tf32 mma.sync GEMM: C[128x128] = A[m0:+128, 0:1024] @ W[0:1024, n0:+128]
// 128 threads = 4 warps (2x2), warp tile 64x64, BK=32, k-step 8.
// ===========================================================================
#define STRA 36    // As [m][k] stride in floats  (frag-load banks 4r+c: perfect)
#define STRB 136   // Bs [k][n] stride in floats  (frag-load banks 8c+r: perfect)

__device__ __forceinline__ uint32_t f2tf32(float f) {
    uint32_t u;
    asm("cvt.rna.tf32.f32 %0, %1;" : "=r"(u) : "f"(f));
    return u;
}

__device__ __forceinline__ void mma_tf32(
    float* c, uint32_t a0, uint32_t a1, uint32_t a2, uint32_t a3,
    uint32_t b0, uint32_t b1)
{
    asm volatile(
        "mma.sync.aligned.m16n8k8.row.col.f32.tf32.tf32.f32 "
        "{%0,%1,%2,%3}, {%4,%5,%6,%7}, {%8,%9}, {%0,%1,%2,%3};"
        : "+f"(c[0]), "+f"(c[1]), "+f"(c[2]), "+f"(c[3])
        : "r"(a0), "r"(a1), "r"(a2), "r"(a3), "r"(b0), "r"(b1));
}

// Compute accumulators for one 128x128 C tile. acc[mi][ni][4].
__device__ __forceinline__ void tc_mainloop(
    const float* __restrict__ A, const float* __restrict__ W,
    int m0, int n0, float acc[4][8][4], float* As, float* Bs)
{
    const int tid = threadIdx.x;
    const int warp = tid >> 5, lane = tid & 31;
    const int wm0 = (warp & 1) * 64;
    const int wn0 = (warp >> 1) * 64;
    const int r = lane >> 2, cq = lane & 3;

    const uint32_t* Asu = (const uint32_t*)As;
    const uint32_t* Bsu = (const uint32_t*)Bs;

#pragma unroll
    for (int mi = 0; mi < 4; mi++)
#pragma unroll
        for (int ni = 0; ni < 8; ni++)
#pragma unroll
            for (int t = 0; t < 4; t++) acc[mi][ni][t] = 0.f;

    float4 av[8], wv[8];
    // prologue: load chunk 0
#pragma unroll
    for (int p = 0; p < 8; p++) {
        int lin = p * 512 + tid * 4;
        av[p] = *(const float4*)(A + (size_t)(m0 + (lin >> 5)) * DD + (lin & 31));
        wv[p] = *(const float4*)(W + (size_t)(lin >> 7) * DD + n0 + (lin & 127));
    }

    for (int c = 0; c < 32; c++) {
        __syncthreads();   // previous chunk's readers done
#pragma unroll
        for (int p = 0; p < 8; p++) {
            int lin = p * 512 + tid * 4;
            { int ar = lin >> 5, ac = lin & 31;
              float4 q; q.x = __uint_as_float(f2tf32(av[p].x));
              q.y = __uint_as_float(f2tf32(av[p].y));
              q.z = __uint_as_float(f2tf32(av[p].z));
              q.w = __uint_as_float(f2tf32(av[p].w));
              *(float4*)(As + ar * STRA + ac) = q; }
            { int kr = lin >> 7, nc = lin & 127;
              float4 q; q.x = __uint_as_float(f2tf32(wv[p].x));
              q.y = __uint_as_float(f2tf32(wv[p].y));
              q.z = __uint_as_float(f2tf32(wv[p].z));
              q.w = __uint_as_float(f2tf32(wv[p].w));
              *(float4*)(Bs + kr * STRB + nc) = q; }
        }
        __syncthreads();

        // prefetch next chunk (clamped; hidden under mma)
        int cn = (c < 31) ? c + 1 : 31;
#pragma unroll
        for (int p = 0; p < 8; p++) {
            int lin = p * 512 + tid * 4;
            av[p] = *(const float4*)(A + (size_t)(m0 + (lin >> 5)) * DD + cn * 32 + (lin & 31));
            wv[p] = *(const float4*)(W + (size_t)(cn * 32 + (lin >> 7)) * DD + n0 + (lin & 127));
        }

#pragma unroll
        for (int ks = 0; ks < 4; ks++) {
            const int k = ks * 8;
            uint32_t af[4][4], bf[8][2];
#pragma unroll
            for (int mi = 0; mi < 4; mi++) {
                int mb = wm0 + mi * 16;
                af[mi][0] = Asu[(mb + r) * STRA + k + cq];
                af[mi][1] = Asu[(mb + r + 8) * STRA + k + cq];
                af[mi][2] = Asu[(mb + r) * STRA + k + cq + 4];
                af[mi][3] = Asu[(mb + r + 8) * STRA + k + cq + 4];
            }
#pragma unroll
            for (int ni = 0; ni < 8; ni++) {
                int nb = wn0 + ni * 8;
                bf[ni][0] = Bsu[(k + cq) * STRB + nb + r];
                bf[ni][1] = Bsu[(k + cq + 4) * STRB + nb + r];
            }
#pragma unroll
            for (int mi = 0; mi < 4; mi++)
#pragma unroll
                for (int ni = 0; ni < 8; ni++)
                    mma_tf32(acc[mi][ni], af[mi][0], af[mi][1], af[mi][2], af[mi][3],
                             bf[ni][0], bf[ni][1]);
        }
    }
}

// ---------------------------------------------------------------------------
// QKV projection. grid=(8, 32, 3), 128 threads. Epilogue remaps to [B,H,S,HD].
// ---------------------------------------------------------------------------
__global__ __launch_bounds__(128) void qkv_mma(
    const float* __restrict__ x,
    const float* __restrict__ Wq, const float* __restrict__ bq,
    const float* __restrict__ Wk, const float* __restrict__ bk,
    const float* __restrict__ Wv, const float* __restrict__ bv)
{
    __shared__ float As[128 * STRA];
    __shared__ float Bs[32 * STRB];

    const int z = blockIdx.z;
    const float* __restrict__ W = (z == 0) ? Wq : (z == 1) ? Wk : Wv;
    const float* __restrict__ bias = (z == 0) ? bq : (z == 1) ? bk : bv;
    float* __restrict__ out = (z == 0) ? g_q : (z == 1) ? g_k : g_v;

    const int m0 = blockIdx.y * 128;
    const int n0 = blockIdx.x * 128;

    float acc[4][8][4];
    tc_mainloop(x, W, m0, n0, acc, As, Bs);

    const int tid = threadIdx.x;
    const int warp = tid >> 5, lane = tid & 31;
    const int wm0 = (warp & 1) * 64;
    const int wn0 = (warp >> 1) * 64;
    const int r = lane >> 2, cq = lane & 3;

#pragma unroll
    for (int mi = 0; mi < 4; mi++) {
#pragma unroll
        for (int ni = 0; ni < 8; ni++) {
            int ncol = n0 + wn0 + ni * 8 + 2 * cq;
            int h = ncol >> 6, d = ncol & 63;
            float b0v = bias[ncol], b1v = bias[ncol + 1];
#pragma unroll
            for (int half = 0; half < 2; half++) {
                int mrow = m0 + wm0 + mi * 16 + r + half * 8;
                int bidx = mrow >> 11, s = mrow & (SS - 1);
                float2 o;
                o.x = acc[mi][ni][half * 2 + 0] + b0v;
                o.y = acc[mi][ni][half * 2 + 1] + b1v;
                *(float2*)(out + (size_t)((bidx * HH + h) * SS + s) * HD + d) = o;
            }
        }
    }
}

// ---------------------------------------------------------------------------
// Output projection. grid=(8, 32), 128 threads.
// ---------------------------------------------------------------------------
__global__ __launch_bounds__(128) void oproj_mma(
    const float* __restrict__ Wo, const float* __restrict__ bo,
    float* __restrict__ out)
{
    __shared__ float As[128 * STRA];
    __shared__ float Bs[32 * STRB];

    const int m0 = blockIdx.y * 128;
    const int n0 = blockIdx.x * 128;

    float acc[4][8][4];
    tc_mainloop(g_att, Wo, m0, n0, acc, As, Bs);

    const int tid = threadIdx.x;
    const int warp = tid >> 5, lane = tid & 31;
    const int wm0 = (warp & 1) * 64;
    const int wn0 = (warp >> 1) * 64;
    const int r = lane >> 2, cq = lane & 3;

#pragma unroll
    for (int mi = 0; mi < 4; mi++) {
#pragma unroll
        for (int ni = 0; ni < 8; ni++) {
            int ncol = n0 + wn0 + ni * 8 + 2 * cq;
            float b0v = bo[ncol], b1v = bo[ncol + 1];
#pragma unroll
            for (int half = 0; half < 2; half++) {
                int mrow = m0 + wm0 + mi * 16 + r + half * 8;
                float2 o;
                o.x = acc[mi][ni][half * 2 + 0] + b0v;
                o.y = acc[mi][ni][half * 2 + 1] + b1v;
                *(float2*)(out + (size_t)mrow * DD + ncol) = o;
            }
        }
    }
}

// ---------------------------------------------------------------------------
// Flash-attention style kernel (unchanged — known good).
// ---------------------------------------------------------------------------
#define SQ 68
#define SP 65

__global__ __launch_bounds__(256) void attn_kernel(const float* __restrict__ mask)
{
    extern __shared__ float smf[];
    float* Qs = smf;
    float* Ks = Qs + 64 * SQ;
    float* Vs = Ks + 64 * SQ;
    float* Ps = Vs + 64 * SQ;
    float* marr = Ps + 64 * SP;
    float* larr = marr + 64;
    float* osc  = larr + 64;
    float* madd = osc + 64;

    const int qt = blockIdx.x, h = blockIdx.y, b = blockIdx.z;
    const int tid = threadIdx.x, tx = tid % 16, ty = tid / 16;

    const float* qbase = g_q + (size_t)((b * HH + h) * SS + qt * 64) * HD;

#pragma unroll
    for (int p = 0; p < 4; p++) {
        int lin = p * 1024 + tid * 4;
        int r = lin / 64, d = lin % 64;
        float4 v = *(const float4*)&qbase[r * 64 + d];
        Qs[(d + 0) * SQ + r] = v.x;
        Qs[(d + 1) * SQ + r] = v.y;
        Qs[(d + 2) * SQ + r] = v.z;
        Qs[(d + 3) * SQ + r] = v.w;
    }
    if (tid < 64) { marr[tid] = -1e30f; larr[tid] = 0.f; }

    float O[4][4];
#pragma unroll
    for (int i = 0; i < 4; i++)
#pragma unroll
        for (int j = 0; j < 4; j++) O[i][j] = 0.f;

    __syncthreads();

    for (int jt = 0; jt <= qt; jt++) {
        const float* kbase = g_k + (size_t)((b * HH + h) * SS + jt * 64) * HD;
        const float* vbase = g_v + (size_t)((b * HH + h) * SS + jt * 64) * HD;
#pragma unroll
        for (int p = 0; p < 4; p++) {
            int lin = p * 1024 + tid * 4;
            int r = lin / 64, d = lin % 64;
            float4 v = *(const float4*)&kbase[r * 64 + d];
            Ks[(d + 0) * SQ + r] = v.x;
            Ks[(d + 1) * SQ + r] = v.y;
            Ks[(d + 2) * SQ + r] = v.z;
            Ks[(d + 3) * SQ + r] = v.w;
            *(float4*)&Vs[r * SQ + d] = *(const float4*)&vbase[r * 64 + d];
        }
        if (tid < 64)
            madd[tid] = (1.f - mask[b * SS + jt * 64 + tid]) * NEG;
        __syncthreads();

        float s[4][4];
#pragma unroll
        for (int i = 0; i < 4; i++)
#pragma unroll
            for (int j = 0; j < 4; j++) s[i][j] = 0.f;
#pragma unroll 8
        for (int d = 0; d < 64; d++) {
            float4 a = *(const float4*)&Qs[d * SQ + ty * 4];
            float4 bvec = *(const float4*)&Ks[d * SQ + tx * 4];
            float ar[4] = {a.x, a.y, a.z, a.w};
            float br[4] = {bvec.x, bvec.y, bvec.z, bvec.w};
#pragma unroll
            for (int i = 0; i < 4; i++)
#pragma unroll
                for (int j = 0; j < 4; j++) s[i][j] += ar[i] * br[j];
        }

        const bool diag = (jt == qt);
#pragma unroll
        for (int i = 0; i < 4; i++) {
            int qg = ty * 4 + i;
#pragma unroll
            for (int j = 0; j < 4; j++) {
                int kl = tx * 4 + j;
                float v;
                if (diag && (kl > qg)) v = NEG;
                else                   v = s[i][j] * 0.125f;
                v += madd[kl];
                Ps[qg * SP + kl] = v;
            }
        }
        __syncthreads();

        if (tid < 64) {
            float mx = -1e30f;
#pragma unroll 8
            for (int k = 0; k < 64; k++) mx = fmaxf(mx, Ps[tid * SP + k]);
            float m_old = marr[tid];
            float m_new = fmaxf(m_old, mx);
            float sum = 0.f;
#pragma unroll 8
            for (int k = 0; k < 64; k++) {
                float p = __expf(Ps[tid * SP + k] - m_new);
                Ps[tid * SP + k] = p;
                sum += p;
            }
            float sc = __expf(m_old - m_new);
            osc[tid] = sc;
            larr[tid] = larr[tid] * sc + sum;
            marr[tid] = m_new;
        }
        __syncthreads();

        float scl[4];
#pragma unroll
        for (int i = 0; i < 4; i++) scl[i] = osc[ty * 4 + i];
#pragma unroll
        for (int i = 0; i < 4; i++)
#pragma unroll
            for (int j = 0; j < 4; j++) O[i][j] *= scl[i];

#pragma unroll 8
        for (int k = 0; k < 64; k++) {
            float4 bvec = *(const float4*)&Vs[k * SQ + tx * 4];
            float br[4] = {bvec.x, bvec.y, bvec.z, bvec.w};
#pragma unroll
            for (int i = 0; i < 4; i++) {
                float a = Ps[(ty * 4 + i) * SP + k];
#pragma unroll
                for (int j = 0; j < 4; j++) O[i][j] += a * br[j];
            }
        }
        __syncthreads();
    }

#pragma unroll
    for (int i = 0; i < 4; i++) {
        int ql = ty * 4 + i;
        int sg = qt * 64 + ql;
        float il = 1.f / larr[ql];
        float4 o;
        o.x = O[i][0] * il;
        o.y = O[i][1] * il;
        o.z = O[i][2] * il;
        o.w = O[i][3] * il;
        *(float4*)&g_att[(size_t)(b * SS + sg) * DD + h * HD + tx * 4] = o;
    }
}

// ---------------------------------------------------------------------------
extern "C" void kernel_launch(void* const* d_in, const int* in_sizes, int n_in,
                              void* d_out, int out_size)
{
    const float* x    = (const float*)d_in[0];
    const float* mask = (const float*)d_in[1];
    const float* Wq   = (const float*)d_in[2];
    const float* bq   = (const float*)d_in[3];
    const float* Wk   = (const float*)d_in[4];
    const float* bk   = (const float*)d_in[5];
    const float* Wv   = (const float*)d_in[6];
    const float* bv   = (const float*)d_in[7];
    const float* Wo   = (const float*)d_in[8];
    const float* bo   = (const float*)d_in[9];
    float* out = (float*)d_out;

    const int smem_bytes = (3 * 64 * SQ + 64 * SP + 4 * 64) * sizeof(float);
    cudaFuncSetAttribute(attn_kernel,
                         cudaFuncAttributeMaxDynamicSharedMemorySize,
                         smem_bytes);

    dim3 gq(DD / 128, (BB * SS) / 128, 3);
    qkv_mma<<<gq, 128>>>(x, Wq, bq, Wk, bk, Wv, bv);

    dim3 ga(SS / 64, HH, BB);
    attn_kernel<<<ga, 256, smem_bytes>>>(mask);

    dim3 go(DD / 128, (BB * SS) / 128);
    oproj_mma<<<go, 128>>>(Wo, bo, out);
}

// round 4
// speedup vs baseline: 2.1501x; 1.2632x over previous
#include <cuda_runtime.h>
#include <cuda_bf16.h>
#include <cstdint>

// Problem constants
#define BB 2
#define SS 2048
#define DD 1024
#define HH 16
#define HD 64
#define NEG (-1.0e9f)

// Scratch (device globals)
__device__ float g_q[BB * HH * SS * HD];     // [B,H,S,HD]
__device__ float g_k[BB * HH * SS * HD];
__device__ float g_v[BB * HH * SS * HD];
__device__ float g_att[BB * SS * DD];        // [B,S,D]

// ===========================================================================
// Common mma helpers
// ===========================================================================
__device__ __forceinline__ uint32_t f2tf32(float f) {
    uint32_t u;
    asm("cvt.rna.tf32.f32 %0, %1;" : "=r"(u) : "f"(f));
    return u;
}
__device__ __forceinline__ float f2tf32f(float f) {
    return __uint_as_float(f2tf32(f));
}

__device__ __forceinline__ void mma_tf32(
    float* c, uint32_t a0, uint32_t a1, uint32_t a2, uint32_t a3,
    uint32_t b0, uint32_t b1)
{
    asm volatile(
        "mma.sync.aligned.m16n8k8.row.col.f32.tf32.tf32.f32 "
        "{%0,%1,%2,%3}, {%4,%5,%6,%7}, {%8,%9}, {%0,%1,%2,%3};"
        : "+f"(c[0]), "+f"(c[1]), "+f"(c[2]), "+f"(c[3])
        : "r"(a0), "r"(a1), "r"(a2), "r"(a3), "r"(b0), "r"(b1));
}

// ===========================================================================
// tf32 mma.sync GEMM (unchanged from R3 — validated)
// ===========================================================================
#define STRA 36
#define STRB 136

__device__ __forceinline__ void tc_mainloop(
    const float* __restrict__ A, const float* __restrict__ W,
    int m0, int n0, float acc[4][8][4], float* As, float* Bs)
{
    const int tid = threadIdx.x;
    const int warp = tid >> 5, lane = tid & 31;
    const int wm0 = (warp & 1) * 64;
    const int wn0 = (warp >> 1) * 64;
    const int r = lane >> 2, cq = lane & 3;

    const uint32_t* Asu = (const uint32_t*)As;
    const uint32_t* Bsu = (const uint32_t*)Bs;

#pragma unroll
    for (int mi = 0; mi < 4; mi++)
#pragma unroll
        for (int ni = 0; ni < 8; ni++)
#pragma unroll
            for (int t = 0; t < 4; t++) acc[mi][ni][t] = 0.f;

    float4 av[8], wv[8];
#pragma unroll
    for (int p = 0; p < 8; p++) {
        int lin = p * 512 + tid * 4;
        av[p] = *(const float4*)(A + (size_t)(m0 + (lin >> 5)) * DD + (lin & 31));
        wv[p] = *(const float4*)(W + (size_t)(lin >> 7) * DD + n0 + (lin & 127));
    }

    for (int c = 0; c < 32; c++) {
        __syncthreads();
#pragma unroll
        for (int p = 0; p < 8; p++) {
            int lin = p * 512 + tid * 4;
            { int ar = lin >> 5, ac = lin & 31;
              float4 q; q.x = f2tf32f(av[p].x); q.y = f2tf32f(av[p].y);
              q.z = f2tf32f(av[p].z); q.w = f2tf32f(av[p].w);
              *(float4*)(As + ar * STRA + ac) = q; }
            { int kr = lin >> 7, nc = lin & 127;
              float4 q; q.x = f2tf32f(wv[p].x); q.y = f2tf32f(wv[p].y);
              q.z = f2tf32f(wv[p].z); q.w = f2tf32f(wv[p].w);
              *(float4*)(Bs + kr * STRB + nc) = q; }
        }
        __syncthreads();

        int cn = (c < 31) ? c + 1 : 31;
#pragma unroll
        for (int p = 0; p < 8; p++) {
            int lin = p * 512 + tid * 4;
            av[p] = *(const float4*)(A + (size_t)(m0 + (lin >> 5)) * DD + cn * 32 + (lin & 31));
            wv[p] = *(const float4*)(W + (size_t)(cn * 32 + (lin >> 7)) * DD + n0 + (lin & 127));
        }

#pragma unroll
        for (int ks = 0; ks < 4; ks++) {
            const int k = ks * 8;
            uint32_t af[4][4], bf[8][2];
#pragma unroll
            for (int mi = 0; mi < 4; mi++) {
                int mb = wm0 + mi * 16;
                af[mi][0] = Asu[(mb + r) * STRA + k + cq];
                af[mi][1] = Asu[(mb + r + 8) * STRA + k + cq];
                af[mi][2] = Asu[(mb + r) * STRA + k + cq + 4];
                af[mi][3] = Asu[(mb + r + 8) * STRA + k + cq + 4];
            }
#pragma unroll
            for (int ni = 0; ni < 8; ni++) {
                int nb = wn0 + ni * 8;
                bf[ni][0] = Bsu[(k + cq) * STRB + nb + r];
                bf[ni][1] = Bsu[(k + cq + 4) * STRB + nb + r];
            }
#pragma unroll
            for (int mi = 0; mi < 4; mi++)
#pragma unroll
                for (int ni = 0; ni < 8; ni++)
                    mma_tf32(acc[mi][ni], af[mi][0], af[mi][1], af[mi][2], af[mi][3],
                             bf[ni][0], bf[ni][1]);
        }
    }
}

__global__ __launch_bounds__(128) void qkv_mma(
    const float* __restrict__ x,
    const float* __restrict__ Wq, const float* __restrict__ bq,
    const float* __restrict__ Wk, const float* __restrict__ bk,
    const float* __restrict__ Wv, const float* __restrict__ bv)
{
    __shared__ float As[128 * STRA];
    __shared__ float Bs[32 * STRB];

    const int z = blockIdx.z;
    const float* __restrict__ W = (z == 0) ? Wq : (z == 1) ? Wk : Wv;
    const float* __restrict__ bias = (z == 0) ? bq : (z == 1) ? bk : bv;
    float* __restrict__ out = (z == 0) ? g_q : (z == 1) ? g_k : g_v;

    const int m0 = blockIdx.y * 128;
    const int n0 = blockIdx.x * 128;

    float acc[4][8][4];
    tc_mainloop(x, W, m0, n0, acc, As, Bs);

    const int tid = threadIdx.x;
    const int warp = tid >> 5, lane = tid & 31;
    const int wm0 = (warp & 1) * 64;
    const int wn0 = (warp >> 1) * 64;
    const int r = lane >> 2, cq = lane & 3;

#pragma unroll
    for (int mi = 0; mi < 4; mi++) {
#pragma unroll
        for (int ni = 0; ni < 8; ni++) {
            int ncol = n0 + wn0 + ni * 8 + 2 * cq;
            int h = ncol >> 6, d = ncol & 63;
            float b0v = bias[ncol], b1v = bias[ncol + 1];
#pragma unroll
            for (int half = 0; half < 2; half++) {
                int mrow = m0 + wm0 + mi * 16 + r + half * 8;
                int bidx = mrow >> 11, s = mrow & (SS - 1);
                float2 o;
                o.x = acc[mi][ni][half * 2 + 0] + b0v;
                o.y = acc[mi][ni][half * 2 + 1] + b1v;
                *(float2*)(out + (size_t)((bidx * HH + h) * SS + s) * HD + d) = o;
            }
        }
    }
}

__global__ __launch_bounds__(128) void oproj_mma(
    const float* __restrict__ Wo, const float* __restrict__ bo,
    float* __restrict__ out)
{
    __shared__ float As[128 * STRA];
    __shared__ float Bs[32 * STRB];

    const int m0 = blockIdx.y * 128;
    const int n0 = blockIdx.x * 128;

    float acc[4][8][4];
    tc_mainloop(g_att, Wo, m0, n0, acc, As, Bs);

    const int tid = threadIdx.x;
    const int warp = tid >> 5, lane = tid & 31;
    const int wm0 = (warp & 1) * 64;
    const int wn0 = (warp >> 1) * 64;
    const int r = lane >> 2, cq = lane & 3;

#pragma unroll
    for (int mi = 0; mi < 4; mi++) {
#pragma unroll
        for (int ni = 0; ni < 8; ni++) {
            int ncol = n0 + wn0 + ni * 8 + 2 * cq;
            float b0v = bo[ncol], b1v = bo[ncol + 1];
#pragma unroll
            for (int half = 0; half < 2; half++) {
                int mrow = m0 + wm0 + mi * 16 + r + half * 8;
                float2 o;
                o.x = acc[mi][ni][half * 2 + 0] + b0v;
                o.y = acc[mi][ni][half * 2 + 1] + b1v;
                *(float2*)(out + (size_t)mrow * DD + ncol) = o;
            }
        }
    }
}

// ===========================================================================
// Flash attention on mma.sync tf32.
// Block: 64 q-rows of one (b,h). 128 threads = 4 warps, each warp 16 q-rows.
// Smem stride 68 (=4 mod 32): all fragment gathers bank-conflict-free.
// ===========================================================================
#define SA 68

__global__ __launch_bounds__(128) void attn_mma(const float* __restrict__ mask)
{
    extern __shared__ float smf[];
    float* Qs = smf;                 // [64][SA]  q rows (tf32)
    float* Ks = Qs + 64 * SA;        // [64][SA]  k rows (tf32)
    float* Vs = Ks + 64 * SA;        // [64][SA]  v rows (tf32)
    float* Ps = Vs + 64 * SA;        // [64][SA]  probabilities (tf32)
    float* madd = Ps + 64 * SA;      // [64] padding-mask additive

    const uint32_t* Qu = (const uint32_t*)Qs;
    const uint32_t* Ku = (const uint32_t*)Ks;
    const uint32_t* Vu = (const uint32_t*)Vs;
    const uint32_t* Pu = (const uint32_t*)Ps;

    const int qt = blockIdx.x, h = blockIdx.y, b = blockIdx.z;
    const int tid = threadIdx.x, warp = tid >> 5, lane = tid & 31;
    const int r = lane >> 2, cq = lane & 3;
    const int wm = warp * 16;

    // Load Q tile -> Qs (tf32)
    const float* qbase = g_q + (size_t)((b * HH + h) * SS + qt * 64) * HD;
#pragma unroll
    for (int p = 0; p < 8; p++) {
        int lin = p * 512 + tid * 4;
        int rr = lin >> 6, dd = lin & 63;
        float4 v = *(const float4*)(qbase + rr * 64 + dd);
        float4 q; q.x = f2tf32f(v.x); q.y = f2tf32f(v.y);
        q.z = f2tf32f(v.z); q.w = f2tf32f(v.w);
        *(float4*)(Qs + rr * SA + dd) = q;
    }

    float o[8][4];
#pragma unroll
    for (int ni = 0; ni < 8; ni++)
#pragma unroll
        for (int t = 0; t < 4; t++) o[ni][t] = 0.f;
    float m0 = -1e30f, m1 = -1e30f, l0 = 0.f, l1 = 0.f;

    for (int jt = 0; jt <= qt; jt++) {
        __syncthreads();   // Qs ready (1st iter); prior Ks/Vs readers done (later)
        const float* kbase = g_k + (size_t)((b * HH + h) * SS + jt * 64) * HD;
        const float* vbase = g_v + (size_t)((b * HH + h) * SS + jt * 64) * HD;
#pragma unroll
        for (int p = 0; p < 8; p++) {
            int lin = p * 512 + tid * 4;
            int rr = lin >> 6, dd = lin & 63;
            float4 kv = *(const float4*)(kbase + rr * 64 + dd);
            float4 q; q.x = f2tf32f(kv.x); q.y = f2tf32f(kv.y);
            q.z = f2tf32f(kv.z); q.w = f2tf32f(kv.w);
            *(float4*)(Ks + rr * SA + dd) = q;
            float4 vv = *(const float4*)(vbase + rr * 64 + dd);
            float4 w; w.x = f2tf32f(vv.x); w.y = f2tf32f(vv.y);
            w.z = f2tf32f(vv.z); w.w = f2tf32f(vv.w);
            *(float4*)(Vs + rr * SA + dd) = w;
        }
        if (tid < 64)
            madd[tid] = (1.f - mask[b * SS + jt * 64 + tid]) * NEG;
        __syncthreads();

        // ---- S = Q @ K^T  (K-transpose done by the col-major frag gather)
        float s[8][4];
#pragma unroll
        for (int ni = 0; ni < 8; ni++)
#pragma unroll
            for (int t = 0; t < 4; t++) s[ni][t] = 0.f;
#pragma unroll
        for (int ks = 0; ks < 8; ks++) {
            const int k = ks * 8;
            uint32_t a0 = Qu[(wm + r) * SA + k + cq];
            uint32_t a1 = Qu[(wm + r + 8) * SA + k + cq];
            uint32_t a2 = Qu[(wm + r) * SA + k + cq + 4];
            uint32_t a3 = Qu[(wm + r + 8) * SA + k + cq + 4];
#pragma unroll
            for (int ni = 0; ni < 8; ni++) {
                uint32_t b0 = Ku[(8 * ni + r) * SA + k + cq];
                uint32_t b1 = Ku[(8 * ni + r) * SA + k + cq + 4];
                mma_tf32(s[ni], a0, a1, a2, a3, b0, b1);
            }
        }

        // ---- scale + masks
        const bool diag = (jt == qt);
        const int row0l = wm + r, row1l = wm + r + 8;
#pragma unroll
        for (int ni = 0; ni < 8; ni++) {
#pragma unroll
            for (int t = 0; t < 4; t++) {
                int col = 8 * ni + 2 * cq + (t & 1);
                int rowl = (t < 2) ? row0l : row1l;
                float v;
                if (diag && (col > rowl)) v = NEG + madd[col];
                else                      v = s[ni][t] * 0.125f + madd[col];
                s[ni][t] = v;
            }
        }

        // ---- online softmax (register fragments)
        float mx0 = -1e30f, mx1 = -1e30f;
#pragma unroll
        for (int ni = 0; ni < 8; ni++) {
            mx0 = fmaxf(mx0, fmaxf(s[ni][0], s[ni][1]));
            mx1 = fmaxf(mx1, fmaxf(s[ni][2], s[ni][3]));
        }
        mx0 = fmaxf(mx0, __shfl_xor_sync(0xffffffff, mx0, 1));
        mx0 = fmaxf(mx0, __shfl_xor_sync(0xffffffff, mx0, 2));
        mx1 = fmaxf(mx1, __shfl_xor_sync(0xffffffff, mx1, 1));
        mx1 = fmaxf(mx1, __shfl_xor_sync(0xffffffff, mx1, 2));

        float nm0 = fmaxf(m0, mx0), nm1 = fmaxf(m1, mx1);
        float sc0 = __expf(m0 - nm0), sc1 = __expf(m1 - nm1);
        float sum0 = 0.f, sum1 = 0.f;
#pragma unroll
        for (int ni = 0; ni < 8; ni++) {
            s[ni][0] = __expf(s[ni][0] - nm0);
            s[ni][1] = __expf(s[ni][1] - nm0);
            s[ni][2] = __expf(s[ni][2] - nm1);
            s[ni][3] = __expf(s[ni][3] - nm1);
            sum0 += s[ni][0] + s[ni][1];
            sum1 += s[ni][2] + s[ni][3];
        }
        sum0 += __shfl_xor_sync(0xffffffff, sum0, 1);
        sum0 += __shfl_xor_sync(0xffffffff, sum0, 2);
        sum1 += __shfl_xor_sync(0xffffffff, sum1, 1);
        sum1 += __shfl_xor_sync(0xffffffff, sum1, 2);

        l0 = l0 * sc0 + sum0;  m0 = nm0;
        l1 = l1 * sc1 + sum1;  m1 = nm1;

#pragma unroll
        for (int ni = 0; ni < 8; ni++) {
            o[ni][0] *= sc0; o[ni][1] *= sc0;
            o[ni][2] *= sc1; o[ni][3] *= sc1;
        }

        // ---- write P (warp-private rows) as tf32, reload as A-fragments
#pragma unroll
        for (int ni = 0; ni < 8; ni++) {
            float2 p0, p1;
            p0.x = f2tf32f(s[ni][0]); p0.y = f2tf32f(s[ni][1]);
            p1.x = f2tf32f(s[ni][2]); p1.y = f2tf32f(s[ni][3]);
            *(float2*)(Ps + row0l * SA + 8 * ni + 2 * cq) = p0;
            *(float2*)(Ps + row1l * SA + 8 * ni + 2 * cq) = p1;
        }
        __syncwarp();

        // ---- O += P @ V
#pragma unroll
        for (int ks = 0; ks < 8; ks++) {
            const int k = ks * 8;
            uint32_t a0 = Pu[(wm + r) * SA + k + cq];
            uint32_t a1 = Pu[(wm + r + 8) * SA + k + cq];
            uint32_t a2 = Pu[(wm + r) * SA + k + cq + 4];
            uint32_t a3 = Pu[(wm + r + 8) * SA + k + cq + 4];
#pragma unroll
            for (int ni = 0; ni < 8; ni++) {
                uint32_t b0 = Vu[(k + cq) * SA + 8 * ni + r];
                uint32_t b1 = Vu[(k + cq + 4) * SA + 8 * ni + r];
                mma_tf32(o[ni], a0, a1, a2, a3, b0, b1);
            }
        }
    }

    // ---- epilogue: normalize and write [B,S,D]
    float inv0 = 1.f / l0, inv1 = 1.f / l1;
    int row0 = qt * 64 + wm + r;
    float* ob0 = g_att + (size_t)(b * SS + row0) * DD + h * HD;
    float* ob1 = g_att + (size_t)(b * SS + row0 + 8) * DD + h * HD;
#pragma unroll
    for (int ni = 0; ni < 8; ni++) {
        int col = 8 * ni + 2 * cq;
        float2 w0, w1;
        w0.x = o[ni][0] * inv0; w0.y = o[ni][1] * inv0;
        w1.x = o[ni][2] * inv1; w1.y = o[ni][3] * inv1;
        *(float2*)(ob0 + col) = w0;
        *(float2*)(ob1 + col) = w1;
    }
}

// ---------------------------------------------------------------------------
extern "C" void kernel_launch(void* const* d_in, const int* in_sizes, int n_in,
                              void* d_out, int out_size)
{
    const float* x    = (const float*)d_in[0];
    const float* mask = (const float*)d_in[1];
    const float* Wq   = (const float*)d_in[2];
    const float* bq   = (const float*)d_in[3];
    const float* Wk   = (const float*)d_in[4];
    const float* bk   = (const float*)d_in[5];
    const float* Wv   = (const float*)d_in[6];
    const float* bv   = (const float*)d_in[7];
    const float* Wo   = (const float*)d_in[8];
    const float* bo   = (const float*)d_in[9];
    float* out = (float*)d_out;

    const int attn_smem = (4 * 64 * SA + 64) * sizeof(float);   // ~69.9 KB
    cudaFuncSetAttribute(attn_mma,
                         cudaFuncAttributeMaxDynamicSharedMemorySize,
                         attn_smem);

    dim3 gq(DD / 128, (BB * SS) / 128, 3);
    qkv_mma<<<gq, 128>>>(x, Wq, bq, Wk, bk, Wv, bv);

    dim3 ga(SS / 64, HH, BB);
    attn_mma<<<ga, 128, attn_smem>>>(mask);

    dim3 go(DD / 128, (BB * SS) / 128);
    oproj_mma<<<go, 128>>>(Wo, bo, out);
}

// round 5
// speedup vs baseline: 2.9775x; 1.3848x over previous
#include <cuda_runtime.h>
#include <cuda_bf16.h>
#include <cstdint>

// Problem constants
#define BB 2
#define SS 2048
#define DD 1024
#define HH 16
#define HD 64
#define NEG (-1.0e9f)

// Scratch (device globals)
__device__ float g_q[BB * HH * SS * HD];     // [B,H,S,HD]
__device__ float g_k[BB * HH * SS * HD];
__device__ float g_v[BB * HH * SS * HD];
__device__ float g_att[BB * SS * DD];        // [B,S,D]

// ===========================================================================
// Common mma helpers
// ===========================================================================
__device__ __forceinline__ uint32_t f2tf32(float f) {
    uint32_t u;
    asm("cvt.rna.tf32.f32 %0, %1;" : "=r"(u) : "f"(f));
    return u;
}
__device__ __forceinline__ float f2tf32f(float f) {
    return __uint_as_float(f2tf32(f));
}

__device__ __forceinline__ void mma_tf32(
    float* c, uint32_t a0, uint32_t a1, uint32_t a2, uint32_t a3,
    uint32_t b0, uint32_t b1)
{
    asm volatile(
        "mma.sync.aligned.m16n8k8.row.col.f32.tf32.tf32.f32 "
        "{%0,%1,%2,%3}, {%4,%5,%6,%7}, {%8,%9}, {%0,%1,%2,%3};"
        : "+f"(c[0]), "+f"(c[1]), "+f"(c[2]), "+f"(c[3])
        : "r"(a0), "r"(a1), "r"(a2), "r"(a3), "r"(b0), "r"(b1));
}

// ===========================================================================
// tf32 mma.sync GEMM, 2-stage double-buffered smem, 1 sync per K-chunk.
// 128 threads = 4 warps (2x2), warp tile 64x64, BK=32.
// ===========================================================================
#define STRA 36
#define STRB 136
#define ASTG (128 * STRA)
#define BSTG (32 * STRB)

__device__ __forceinline__ void tc_mainloop(
    const float* __restrict__ A, const float* __restrict__ W,
    int m0, int n0, float acc[4][8][4], float* AsB, float* BsB)
{
    const int tid = threadIdx.x;
    const int warp = tid >> 5, lane = tid & 31;
    const int wm0 = (warp & 1) * 64;
    const int wn0 = (warp >> 1) * 64;
    const int r = lane >> 2, cq = lane & 3;

#pragma unroll
    for (int mi = 0; mi < 4; mi++)
#pragma unroll
        for (int ni = 0; ni < 8; ni++)
#pragma unroll
            for (int t = 0; t < 4; t++) acc[mi][ni][t] = 0.f;

    float4 av[8], wv[8];
    // prologue: LDG chunk 0
#pragma unroll
    for (int p = 0; p < 8; p++) {
        int lin = p * 512 + tid * 4;
        av[p] = *(const float4*)(A + (size_t)(m0 + (lin >> 5)) * DD + (lin & 31));
        wv[p] = *(const float4*)(W + (size_t)(lin >> 7) * DD + n0 + (lin & 127));
    }
    // STS chunk 0 -> stage 0
    {
        float* As = AsB;
        float* Bs = BsB;
#pragma unroll
        for (int p = 0; p < 8; p++) {
            int lin = p * 512 + tid * 4;
            { int ar = lin >> 5, ac = lin & 31;
              float4 q; q.x = f2tf32f(av[p].x); q.y = f2tf32f(av[p].y);
              q.z = f2tf32f(av[p].z); q.w = f2tf32f(av[p].w);
              *(float4*)(As + ar * STRA + ac) = q; }
            { int kr = lin >> 7, nc = lin & 127;
              float4 q; q.x = f2tf32f(wv[p].x); q.y = f2tf32f(wv[p].y);
              q.z = f2tf32f(wv[p].z); q.w = f2tf32f(wv[p].w);
              *(float4*)(Bs + kr * STRB + nc) = q; }
        }
    }

    for (int c = 0; c < 32; c++) {
        __syncthreads();   // stage (c&1) visible; prior readers of (c+1)&1 done

        // prefetch next chunk (LDG in flight under the mma block)
        if (c < 31) {
#pragma unroll
            for (int p = 0; p < 8; p++) {
                int lin = p * 512 + tid * 4;
                av[p] = *(const float4*)(A + (size_t)(m0 + (lin >> 5)) * DD
                                         + (c + 1) * 32 + (lin & 31));
                wv[p] = *(const float4*)(W + (size_t)((c + 1) * 32 + (lin >> 7)) * DD
                                         + n0 + (lin & 127));
            }
        }

        const uint32_t* Asu = (const uint32_t*)(AsB + (c & 1) * ASTG);
        const uint32_t* Bsu = (const uint32_t*)(BsB + (c & 1) * BSTG);
#pragma unroll
        for (int ks = 0; ks < 4; ks++) {
            const int k = ks * 8;
            uint32_t af[4][4], bf[8][2];
#pragma unroll
            for (int mi = 0; mi < 4; mi++) {
                int mb = wm0 + mi * 16;
                af[mi][0] = Asu[(mb + r) * STRA + k + cq];
                af[mi][1] = Asu[(mb + r + 8) * STRA + k + cq];
                af[mi][2] = Asu[(mb + r) * STRA + k + cq + 4];
                af[mi][3] = Asu[(mb + r + 8) * STRA + k + cq + 4];
            }
#pragma unroll
            for (int ni = 0; ni < 8; ni++) {
                int nb = wn0 + ni * 8;
                bf[ni][0] = Bsu[(k + cq) * STRB + nb + r];
                bf[ni][1] = Bsu[(k + cq + 4) * STRB + nb + r];
            }
#pragma unroll
            for (int mi = 0; mi < 4; mi++)
#pragma unroll
                for (int ni = 0; ni < 8; ni++)
                    mma_tf32(acc[mi][ni], af[mi][0], af[mi][1], af[mi][2], af[mi][3],
                             bf[ni][0], bf[ni][1]);
        }

        // STS next chunk into the other stage (after mma: LDG latency hidden)
        if (c < 31) {
            float* As = AsB + ((c + 1) & 1) * ASTG;
            float* Bs = BsB + ((c + 1) & 1) * BSTG;
#pragma unroll
            for (int p = 0; p < 8; p++) {
                int lin = p * 512 + tid * 4;
                { int ar = lin >> 5, ac = lin & 31;
                  float4 q; q.x = f2tf32f(av[p].x); q.y = f2tf32f(av[p].y);
                  q.z = f2tf32f(av[p].z); q.w = f2tf32f(av[p].w);
                  *(float4*)(As + ar * STRA + ac) = q; }
                { int kr = lin >> 7, nc = lin & 127;
                  float4 q; q.x = f2tf32f(wv[p].x); q.y = f2tf32f(wv[p].y);
                  q.z = f2tf32f(wv[p].z); q.w = f2tf32f(wv[p].w);
                  *(float4*)(Bs + kr * STRB + nc) = q; }
            }
        }
    }
}

// ---------------------------------------------------------------------------
// QKV projection. grid=(8, 32, 3), 128 threads.
// ---------------------------------------------------------------------------
__global__ __launch_bounds__(128) void qkv_mma(
    const float* __restrict__ x,
    const float* __restrict__ Wq, const float* __restrict__ bq,
    const float* __restrict__ Wk, const float* __restrict__ bk,
    const float* __restrict__ Wv, const float* __restrict__ bv)
{
    extern __shared__ float dsm[];
    float* AsB = dsm;
    float* BsB = dsm + 2 * ASTG;

    const int z = blockIdx.z;
    const float* __restrict__ W = (z == 0) ? Wq : (z == 1) ? Wk : Wv;
    const float* __restrict__ bias = (z == 0) ? bq : (z == 1) ? bk : bv;
    float* __restrict__ out = (z == 0) ? g_q : (z == 1) ? g_k : g_v;

    const int m0 = blockIdx.y * 128;
    const int n0 = blockIdx.x * 128;

    float acc[4][8][4];
    tc_mainloop(x, W, m0, n0, acc, AsB, BsB);

    const int tid = threadIdx.x;
    const int warp = tid >> 5, lane = tid & 31;
    const int wm0 = (warp & 1) * 64;
    const int wn0 = (warp >> 1) * 64;
    const int r = lane >> 2, cq = lane & 3;

#pragma unroll
    for (int mi = 0; mi < 4; mi++) {
#pragma unroll
        for (int ni = 0; ni < 8; ni++) {
            int ncol = n0 + wn0 + ni * 8 + 2 * cq;
            int h = ncol >> 6, d = ncol & 63;
            float b0v = bias[ncol], b1v = bias[ncol + 1];
#pragma unroll
            for (int half = 0; half < 2; half++) {
                int mrow = m0 + wm0 + mi * 16 + r + half * 8;
                int bidx = mrow >> 11, s = mrow & (SS - 1);
                float2 o;
                o.x = acc[mi][ni][half * 2 + 0] + b0v;
                o.y = acc[mi][ni][half * 2 + 1] + b1v;
                *(float2*)(out + (size_t)((bidx * HH + h) * SS + s) * HD + d) = o;
            }
        }
    }
}

// ---------------------------------------------------------------------------
// Output projection. grid=(8, 32), 128 threads.
// ---------------------------------------------------------------------------
__global__ __launch_bounds__(128) void oproj_mma(
    const float* __restrict__ Wo, const float* __restrict__ bo,
    float* __restrict__ out)
{
    extern __shared__ float dsm[];
    float* AsB = dsm;
    float* BsB = dsm + 2 * ASTG;

    const int m0 = blockIdx.y * 128;
    const int n0 = blockIdx.x * 128;

    float acc[4][8][4];
    tc_mainloop(g_att, Wo, m0, n0, acc, AsB, BsB);

    const int tid = threadIdx.x;
    const int warp = tid >> 5, lane = tid & 31;
    const int wm0 = (warp & 1) * 64;
    const int wn0 = (warp >> 1) * 64;
    const int r = lane >> 2, cq = lane & 3;

#pragma unroll
    for (int mi = 0; mi < 4; mi++) {
#pragma unroll
        for (int ni = 0; ni < 8; ni++) {
            int ncol = n0 + wn0 + ni * 8 + 2 * cq;
            float b0v = bo[ncol], b1v = bo[ncol + 1];
#pragma unroll
            for (int half = 0; half < 2; half++) {
                int mrow = m0 + wm0 + mi * 16 + r + half * 8;
                float2 o;
                o.x = acc[mi][ni][half * 2 + 0] + b0v;
                o.y = acc[mi][ni][half * 2 + 1] + b1v;
                *(float2*)(out + (size_t)mrow * DD + ncol) = o;
            }
        }
    }
}

// ===========================================================================
// Flash attention on mma.sync tf32.
// Block: 128 q-rows of one (b,h). 256 threads = 8 warps, each warp 16 q-rows.
// K/V tiles of 64 rows shared by all 8 warps (halved load traffic per MMA).
// ===========================================================================
#define SA 68
#define QR 128

__global__ __launch_bounds__(256, 2) void attn_mma(const float* __restrict__ mask)
{
    extern __shared__ float smf[];
    float* Qs = smf;                 // [128][SA]
    float* Ks = Qs + QR * SA;        // [64][SA]
    float* Vs = Ks + 64 * SA;        // [64][SA]
    float* Ps = Vs + 64 * SA;        // [128][SA]
    float* madd = Ps + QR * SA;      // [64]

    const uint32_t* Qu = (const uint32_t*)Qs;
    const uint32_t* Ku = (const uint32_t*)Ks;
    const uint32_t* Vu = (const uint32_t*)Vs;
    const uint32_t* Pu = (const uint32_t*)Ps;

    const int qt = gridDim.x - 1 - blockIdx.x;   // big tiles scheduled first
    const int h = blockIdx.y, b = blockIdx.z;
    const int tid = threadIdx.x, warp = tid >> 5, lane = tid & 31;
    const int r = lane >> 2, cq = lane & 3;
    const int wm = warp * 16;
    const int q0 = qt * QR;

    // Load Q tile (tf32): 128 rows x 64
    const float* qbase = g_q + (size_t)((b * HH + h) * SS + q0) * HD;
#pragma unroll
    for (int p = 0; p < 8; p++) {
        int lin = p * 1024 + tid * 4;
        int rr = lin >> 6, dd = lin & 63;
        float4 v = *(const float4*)(qbase + rr * 64 + dd);
        float4 q; q.x = f2tf32f(v.x); q.y = f2tf32f(v.y);
        q.z = f2tf32f(v.z); q.w = f2tf32f(v.w);
        *(float4*)(Qs + rr * SA + dd) = q;
    }

    float o[8][4];
#pragma unroll
    for (int ni = 0; ni < 8; ni++)
#pragma unroll
        for (int t = 0; t < 4; t++) o[ni][t] = 0.f;
    float m0 = -1e30f, m1 = -1e30f, l0 = 0.f, l1 = 0.f;

    const int jt_max = 2 * qt + 1;
    const int rowg0 = q0 + wm + r;
    const int rowg1 = rowg0 + 8;

    for (int jt = 0; jt <= jt_max; jt++) {
        __syncthreads();   // Qs ready (1st iter); prior Ks/Vs readers done
        const float* kbase = g_k + (size_t)((b * HH + h) * SS + jt * 64) * HD;
        const float* vbase = g_v + (size_t)((b * HH + h) * SS + jt * 64) * HD;
#pragma unroll
        for (int p = 0; p < 4; p++) {
            int lin = p * 1024 + tid * 4;
            int rr = lin >> 6, dd = lin & 63;
            float4 kv = *(const float4*)(kbase + rr * 64 + dd);
            float4 q; q.x = f2tf32f(kv.x); q.y = f2tf32f(kv.y);
            q.z = f2tf32f(kv.z); q.w = f2tf32f(kv.w);
            *(float4*)(Ks + rr * SA + dd) = q;
            float4 vv = *(const float4*)(vbase + rr * 64 + dd);
            float4 w; w.x = f2tf32f(vv.x); w.y = f2tf32f(vv.y);
            w.z = f2tf32f(vv.z); w.w = f2tf32f(vv.w);
            *(float4*)(Vs + rr * SA + dd) = w;
        }
        if (tid < 64)
            madd[tid] = (1.f - mask[b * SS + jt * 64 + tid]) * NEG;
        __syncthreads();

        // ---- S = Q @ K^T
        float s[8][4];
#pragma unroll
        for (int ni = 0; ni < 8; ni++)
#pragma unroll
            for (int t = 0; t < 4; t++) s[ni][t] = 0.f;
#pragma unroll
        for (int ks = 0; ks < 8; ks++) {
            const int k = ks * 8;
            uint32_t a0 = Qu[(wm + r) * SA + k + cq];
            uint32_t a1 = Qu[(wm + r + 8) * SA + k + cq];
            uint32_t a2 = Qu[(wm + r) * SA + k + cq + 4];
            uint32_t a3 = Qu[(wm + r + 8) * SA + k + cq + 4];
#pragma unroll
            for (int ni = 0; ni < 8; ni++) {
                uint32_t b0 = Ku[(8 * ni + r) * SA + k + cq];
                uint32_t b1 = Ku[(8 * ni + r) * SA + k + cq + 4];
                mma_tf32(s[ni], a0, a1, a2, a3, b0, b1);
            }
        }

        // ---- scale + causal (global predicate) + padding mask
        const bool part = (jt >= 2 * qt);    // only last two tiles are partial
        const int colb = jt * 64;
#pragma unroll
        for (int ni = 0; ni < 8; ni++) {
#pragma unroll
            for (int t = 0; t < 4; t++) {
                int col = 8 * ni + 2 * cq + (t & 1);
                int rowg = (t < 2) ? rowg0 : rowg1;
                float v;
                if (part && (colb + col > rowg)) v = NEG + madd[col];
                else                             v = s[ni][t] * 0.125f + madd[col];
                s[ni][t] = v;
            }
        }

        // ---- online softmax (register fragments)
        float mx0 = -1e30f, mx1 = -1e30f;
#pragma unroll
        for (int ni = 0; ni < 8; ni++) {
            mx0 = fmaxf(mx0, fmaxf(s[ni][0], s[ni][1]));
            mx1 = fmaxf(mx1, fmaxf(s[ni][2], s[ni][3]));
        }
        mx0 = fmaxf(mx0, __shfl_xor_sync(0xffffffff, mx0, 1));
        mx0 = fmaxf(mx0, __shfl_xor_sync(0xffffffff, mx0, 2));
        mx1 = fmaxf(mx1, __shfl_xor_sync(0xffffffff, mx1, 1));
        mx1 = fmaxf(mx1, __shfl_xor_sync(0xffffffff, mx1, 2));

        float nm0 = fmaxf(m0, mx0), nm1 = fmaxf(m1, mx1);
        float sc0 = __expf(m0 - nm0), sc1 = __expf(m1 - nm1);
        float sum0 = 0.f, sum1 = 0.f;
#pragma unroll
        for (int ni = 0; ni < 8; ni++) {
            s[ni][0] = __expf(s[ni][0] - nm0);
            s[ni][1] = __expf(s[ni][1] - nm0);
            s[ni][2] = __expf(s[ni][2] - nm1);
            s[ni][3] = __expf(s[ni][3] - nm1);
            sum0 += s[ni][0] + s[ni][1];
            sum1 += s[ni][2] + s[ni][3];
        }
        sum0 += __shfl_xor_sync(0xffffffff, sum0, 1);
        sum0 += __shfl_xor_sync(0xffffffff, sum0, 2);
        sum1 += __shfl_xor_sync(0xffffffff, sum1, 1);
        sum1 += __shfl_xor_sync(0xffffffff, sum1, 2);

        l0 = l0 * sc0 + sum0;  m0 = nm0;
        l1 = l1 * sc1 + sum1;  m1 = nm1;

#pragma unroll
        for (int ni = 0; ni < 8; ni++) {
            o[ni][0] *= sc0; o[ni][1] *= sc0;
            o[ni][2] *= sc1; o[ni][3] *= sc1;
        }

        // ---- write P (warp-private rows) as tf32, reload as A-fragments
        const int row0l = wm + r, row1l = wm + r + 8;
#pragma unroll
        for (int ni = 0; ni < 8; ni++) {
            float2 p0, p1;
            p0.x = f2tf32f(s[ni][0]); p0.y = f2tf32f(s[ni][1]);
            p1.x = f2tf32f(s[ni][2]); p1.y = f2tf32f(s[ni][3]);
            *(float2*)(Ps + row0l * SA + 8 * ni + 2 * cq) = p0;
            *(float2*)(Ps + row1l * SA + 8 * ni + 2 * cq) = p1;
        }
        __syncwarp();

        // ---- O += P @ V
#pragma unroll
        for (int ks = 0; ks < 8; ks++) {
            const int k = ks * 8;
            uint32_t a0 = Pu[(wm + r) * SA + k + cq];
            uint32_t a1 = Pu[(wm + r + 8) * SA + k + cq];
            uint32_t a2 = Pu[(wm + r) * SA + k + cq + 4];
            uint32_t a3 = Pu[(wm + r + 8) * SA + k + cq + 4];
#pragma unroll
            for (int ni = 0; ni < 8; ni++) {
                uint32_t b0 = Vu[(k + cq) * SA + 8 * ni + r];
                uint32_t b1 = Vu[(k + cq + 4) * SA + 8 * ni + r];
                mma_tf32(o[ni], a0, a1, a2, a3, b0, b1);
            }
        }
    }

    // ---- epilogue: normalize and write [B,S,D]
    float inv0 = 1.f / l0, inv1 = 1.f / l1;
    float* ob0 = g_att + (size_t)(b * SS + rowg0 - 0) * DD + h * HD;
    float* ob1 = g_att + (size_t)(b * SS + rowg1 - 0) * DD + h * HD;
#pragma unroll
    for (int ni = 0; ni < 8; ni++) {
        int col = 8 * ni + 2 * cq;
        float2 w0, w1;
        w0.x = o[ni][0] * inv0; w0.y = o[ni][1] * inv0;
        w1.x = o[ni][2] * inv1; w1.y = o[ni][3] * inv1;
        *(float2*)(ob0 + col) = w0;
        *(float2*)(ob1 + col) = w1;
    }
}

// ---------------------------------------------------------------------------
extern "C" void kernel_launch(void* const* d_in, const int* in_sizes, int n_in,
                              void* d_out, int out_size)
{
    const float* x    = (const float*)d_in[0];
    const float* mask = (const float*)d_in[1];
    const float* Wq   = (const float*)d_in[2];
    const float* bq   = (const float*)d_in[3];
    const float* Wk   = (const float*)d_in[4];
    const float* bk   = (const float*)d_in[5];
    const float* Wv   = (const float*)d_in[6];
    const float* bv   = (const float*)d_in[7];
    const float* Wo   = (const float*)d_in[8];
    const float* bo   = (const float*)d_in[9];
    float* out = (float*)d_out;

    const int gemm_smem = (2 * ASTG + 2 * BSTG) * sizeof(float);        // 71.7 KB
    const int attn_smem = (2 * QR * SA + 2 * 64 * SA + 64) * sizeof(float); // 104.7 KB
    cudaFuncSetAttribute(qkv_mma,  cudaFuncAttributeMaxDynamicSharedMemorySize, gemm_smem);
    cudaFuncSetAttribute(oproj_mma, cudaFuncAttributeMaxDynamicSharedMemorySize, gemm_smem);
    cudaFuncSetAttribute(attn_mma, cudaFuncAttributeMaxDynamicSharedMemorySize, attn_smem);

    dim3 gq(DD / 128, (BB * SS) / 128, 3);
    qkv_mma<<<gq, 128, gemm_smem>>>(x, Wq, bq, Wk, bk, Wv, bv);

    dim3 ga(SS / QR, HH, BB);
    attn_mma<<<ga, 256, attn_smem>>>(mask);

    dim3 go(DD / 128, (BB * SS) / 128);
    oproj_mma<<<go, 128, gemm_smem>>>(Wo, bo, out);
}